// round 8
// baseline (speedup 1.0000x reference)
#include <cuda_runtime.h>
#include <math.h>

// Problem constants
#define M_TOT 32768            // 512*64 matrices
#define NMAT 32                // matrix side
#define BLOCKS 512
#define THREADS 256
#define WARPS_PER_BLOCK 8
#define NWARPS_TOTAL (BLOCKS * WARPS_PER_BLOCK)   // 4096 -> 8 matrices/warp
#define ROWSTRIDE 33           // padded row stride (bank-conflict free)
#define PART_ENTRIES (32 * ROWSTRIDE)             // 1056 (32 coords + sq per lane)

// Scratch (static device arrays; no runtime allocation allowed)
__device__ float g_L[(size_t)M_TOT * 1024];       // Cholesky factors, 134 MB
__device__ float g_part[BLOCKS * PART_ENTRIES];   // per-block partial sums
__device__ float g_sums[PART_ENTRIES];            // fully reduced sums
__device__ float g_stats[1025];                   // mean[32*32] (diag = logd mean) + factor

// ---------------------------------------------------------------------------
// Pass 1: warp-per-matrix Cholesky + Log-Cholesky statistic accumulation.
// Lane i owns row i of the matrix in registers. Right-looking Cholesky with
// shfl column broadcasts. Upper triangle self-zeroes (lik=0 for lane<k).
// ---------------------------------------------------------------------------
__global__ void __launch_bounds__(THREADS) chol_pass1(const float* __restrict__ X) {
    __shared__ float sred[WARPS_PER_BLOCK * PART_ENTRIES];  // 33.8 KB
    const int lane = threadIdx.x & 31;
    const int wl   = threadIdx.x >> 5;
    const int gw   = blockIdx.x * WARPS_PER_BLOCK + wl;

    float acc[32];
#pragma unroll
    for (int j = 0; j < 32; j++) acc[j] = 0.f;
    float accsq = 0.f;

    for (int m = gw; m < M_TOT; m += NWARPS_TOTAL) {
        // load row i (vectorized, 128B per lane)
        float a[32];
        const float4* src = reinterpret_cast<const float4*>(X + (size_t)m * 1024 + lane * 32);
#pragma unroll
        for (int q = 0; q < 8; q++) {
            float4 v = src[q];
            a[4*q+0] = v.x; a[4*q+1] = v.y; a[4*q+2] = v.z; a[4*q+3] = v.w;
        }

        float mydiag = 1.f;
#pragma unroll
        for (int k = 0; k < 32; k++) {
            float akk = __shfl_sync(0xffffffffu, a[k], k);
            float d   = sqrtf(akk);
            float lik = a[k] / d;            // lane==k: akk/d == d
            if (lane < k)  lik = 0.f;        // zero strictly-upper column entry
            if (lane == k) { lik = d; mydiag = d; }
            a[k] = lik;
            // rank-1 update of trailing submatrix (rows); column k broadcast via shfl
#pragma unroll
            for (int j = k + 1; j < 32; j++) {
                float ljk = __shfl_sync(0xffffffffu, lik, j);
                a[j] -= lik * ljk;
            }
        }
        float logd = logf(mydiag);

        // persist L row (upper already zero, diag = d)
        float4* dst = reinterpret_cast<float4*>(g_L + (size_t)m * 1024 + lane * 32);
#pragma unroll
        for (int q = 0; q < 8; q++) {
            float4 v;
            v.x = a[4*q+0]; v.y = a[4*q+1]; v.z = a[4*q+2]; v.w = a[4*q+3];
            dst[q] = v;
        }

        // accumulate Log-Cholesky coords: strict lower entries + logd in the diag slot
#pragma unroll
        for (int j = 0; j < 32; j++) {
            float v = (j < lane) ? a[j] : ((j == lane) ? logd : 0.f);
            acc[j] += v;
            accsq  += v * v;
        }
    }

    // per-warp accumulators -> shared, then block reduction -> g_part
#pragma unroll
    for (int j = 0; j < 32; j++)
        sred[wl * PART_ENTRIES + lane * ROWSTRIDE + j] = acc[j];
    sred[wl * PART_ENTRIES + lane * ROWSTRIDE + 32] = accsq;
    __syncthreads();

    for (int e = threadIdx.x; e < PART_ENTRIES; e += THREADS) {
        float s = 0.f;
#pragma unroll
        for (int w = 0; w < WARPS_PER_BLOCK; w++) s += sred[w * PART_ENTRIES + e];
        g_part[blockIdx.x * PART_ENTRIES + e] = s;
    }
}

// ---------------------------------------------------------------------------
// k2a: deterministic tree reduction of 512 block partials per entry.
// ---------------------------------------------------------------------------
__global__ void reduce2a() {
    __shared__ float red[BLOCKS];
    const int e = blockIdx.x;
    red[threadIdx.x] = g_part[threadIdx.x * PART_ENTRIES + e];
    __syncthreads();
#pragma unroll
    for (int s = BLOCKS / 2; s > 0; s >>= 1) {
        if ((int)threadIdx.x < s) red[threadIdx.x] += red[threadIdx.x + s];
        __syncthreads();
    }
    if (threadIdx.x == 0) g_sums[e] = red[0];
}

// ---------------------------------------------------------------------------
// k2b: means, variance = E||x||^2 - ||Ex||^2, factor = s / sqrt(var).
// ---------------------------------------------------------------------------
__global__ void stats_pass(const float* __restrict__ s_in) {
    __shared__ float red[1024];
    const int t = threadIdx.x;               // 1024 threads
    const int i = t >> 5, j = t & 31;
    const float invM = 1.0f / (float)M_TOT;

    float mean = g_sums[i * ROWSTRIDE + j] * invM;   // 0 for strictly-upper slots
    g_stats[i * 32 + j] = mean;
    float val = -mean * mean;
    if (t < 32) val += g_sums[t * ROWSTRIDE + 32] * invM;  // E||x||^2 contribution
    red[t] = val;
    __syncthreads();
#pragma unroll
    for (int s = 512; s > 0; s >>= 1) {
        if (t < s) red[t] += red[t + s];
        __syncthreads();
    }
    if (t == 0) {
        float var = red[0];
        g_stats[1024] = s_in[0] / sqrtf(var);
    }
}

// ---------------------------------------------------------------------------
// Pass 3: center + geodesic rescale, then X_out = L_out L_out^T.
// Warp-per-matrix; L_out tile in padded smem (broadcast reads), triangular
// dot products (k <= j; rows implicitly truncated since b[k]=0 for k>lane).
// ---------------------------------------------------------------------------
__global__ void __launch_bounds__(THREADS) out_pass(float* __restrict__ out) {
    __shared__ float smean[PART_ENTRIES];                   // padded mean (stride 33)
    __shared__ float tile[WARPS_PER_BLOCK * PART_ENTRIES];  // 33.8 KB
    __shared__ float sfac;

    for (int e = threadIdx.x; e < 1024; e += THREADS) {
        int mi = e >> 5, mj = e & 31;
        smean[mi * ROWSTRIDE + mj] = g_stats[e];
    }
    if (threadIdx.x == 0) sfac = g_stats[1024];
    __syncthreads();
    const float factor = sfac;

    const int lane = threadIdx.x & 31;
    const int wl   = threadIdx.x >> 5;
    const int gw   = blockIdx.x * WARPS_PER_BLOCK + wl;
    float* mytile  = tile + wl * PART_ENTRIES;

    for (int m = gw; m < M_TOT; m += NWARPS_TOTAL) {
        float a[32];
        const float4* src = reinterpret_cast<const float4*>(g_L + (size_t)m * 1024 + lane * 32);
#pragma unroll
        for (int q = 0; q < 8; q++) {
            float4 v = src[q];
            a[4*q+0] = v.x; a[4*q+1] = v.y; a[4*q+2] = v.z; a[4*q+3] = v.w;
        }
        // extract my diagonal element (compile-time-indexed selects)
        float d = 1.f;
#pragma unroll
        for (int j = 0; j < 32; j++) if (j == lane) d = a[j];

        const float logdc = logf(d) - smean[lane * ROWSTRIDE + lane];
        const float edc   = expf(factor * logdc);

        float b[32];
#pragma unroll
        for (int j = 0; j < 32; j++) {
            float v = (j < lane) ? factor * (a[j] - smean[lane * ROWSTRIDE + j]) : 0.f;
            if (j == lane) v = edc;
            b[j] = v;
        }

        // L_out tile to shared (conflict-free: bank = (lane + j) % 32)
#pragma unroll
        for (int j = 0; j < 32; j++) mytile[lane * ROWSTRIDE + j] = b[j];
        __syncwarp();

        // row i of X_out: o[j] = sum_{k<=j} b[k] * L_out[j][k] (b[k]=0 for k>i)
        float o[32];
#pragma unroll
        for (int j = 0; j < 32; j++) {
            float s = 0.f;
#pragma unroll
            for (int k = 0; k <= j; k++) s += b[k] * mytile[j * ROWSTRIDE + k];
            o[j] = s;
        }
        __syncwarp();   // tile reuse guard for next matrix

        float4* dst = reinterpret_cast<float4*>(out + (size_t)m * 1024 + lane * 32);
#pragma unroll
        for (int q = 0; q < 8; q++) {
            float4 v;
            v.x = o[4*q+0]; v.y = o[4*q+1]; v.z = o[4*q+2]; v.w = o[4*q+3];
            dst[q] = v;
        }
    }
}

extern "C" void kernel_launch(void* const* d_in, const int* in_sizes, int n_in,
                              void* d_out, int out_size) {
    const float* X = (const float*)d_in[0];
    const float* s = (const float*)d_in[1];
    float* out = (float*)d_out;

    chol_pass1<<<BLOCKS, THREADS>>>(X);
    reduce2a<<<PART_ENTRIES, BLOCKS>>>();
    stats_pass<<<1, 1024>>>(s);
    out_pass<<<BLOCKS, THREADS>>>(out);
}

// round 9
// speedup vs baseline: 1.6121x; 1.6121x over previous
#include <cuda_runtime.h>
#include <math.h>

// Problem constants
#define M_TOT 32768            // 512*64 matrices
#define BLOCKS 512
#define THREADS 256
#define WPB 8
#define NWARPS (BLOCKS * WPB)  // 4096 warps -> 8 matrices each
#define TS 36                  // tile row stride in floats (16B-aligned, conflict-free)
#define TS4 9                  // tile row stride in float4
#define PSTRIDE 33             // stats entry stride
#define PART_ENTRIES (32 * PSTRIDE)   // 1056

// Scratch (static device arrays; no runtime allocation allowed)
__device__ float g_L[(size_t)M_TOT * 1024];        // Cholesky factors, COLUMN-major per matrix
__device__ float g_part[PART_ENTRIES * BLOCKS];    // per-block partials, [entry][block]
__device__ float g_sums[PART_ENTRIES];
__device__ float g_stats[1025];                    // mean[32*32] (diag slot = logd mean) + factor

// ---------------------------------------------------------------------------
// Pass 1: coalesced load + smem transpose, warp-per-matrix Cholesky with
// shared-memory column broadcasts (float4), direct coalesced column-major
// store of L, Log-Cholesky statistics accumulation.
// ---------------------------------------------------------------------------
__global__ void __launch_bounds__(THREADS) chol_pass1(const float* __restrict__ X) {
    __shared__ float4 sbuf[WPB * 304];   // per warp: 288 tile f4 + 16 colbuf f4 (2 x 32 floats)
    const int lane = threadIdx.x & 31;
    const int wl   = threadIdx.x >> 5;
    float4* tile = sbuf + wl * 304;
    float*  colf = (float*)(tile + 288);
    const int gw = blockIdx.x * WPB + wl;

    float acc[32];
#pragma unroll
    for (int j = 0; j < 32; j++) acc[j] = 0.f;
    float accsq = 0.f;

    for (int m = gw; m < M_TOT; m += NWARPS) {
        // coalesced load of X, transpose through smem (row-major tile, conflict-free)
        const float4* xs = (const float4*)(X + (size_t)m * 1024);
#pragma unroll
        for (int q = 0; q < 8; q++) {
            float4 v = xs[q * 32 + lane];                       // row 4q+lane/8, cols 4(lane&7)..
            tile[(4 * q + (lane >> 3)) * TS4 + (lane & 7)] = v;
        }
        __syncwarp();
        // own row into registers (conflict-free LDS.128)
        float a[32];
#pragma unroll
        for (int q = 0; q < 8; q++) {
            float4 v = tile[lane * TS4 + q];
            a[4*q+0] = v.x; a[4*q+1] = v.y; a[4*q+2] = v.z; a[4*q+3] = v.w;
        }

        float* gl = g_L + (size_t)m * 1024;
        float mydiag = 1.f;
#pragma unroll
        for (int k = 0; k < 32; k++) {
            float akk  = __shfl_sync(0xffffffffu, a[k], k);
            float rinv = rsqrtf(akk);
            float lik  = a[k] * rinv;           // lane==k -> sqrt(akk)
            if (lane < k) lik = 0.f;
            if (lane == k) mydiag = lik;
            a[k] = lik;
            gl[k * 32 + lane] = lik;            // coalesced column-major store of L
            float* cb = colf + ((k & 1) << 5);  // double-buffered column broadcast
            cb[lane] = lik;
            __syncwarp();
            // rank-1 update via broadcast float4 reads of column k
#pragma unroll
            for (int q = (k + 1) / 4; q < 8; q++) {
                float4 c = ((const float4*)cb)[q];
                if (4*q+0 > k) a[4*q+0] -= lik * c.x;
                if (4*q+1 > k) a[4*q+1] -= lik * c.y;
                if (4*q+2 > k) a[4*q+2] -= lik * c.z;
                if (4*q+3 > k) a[4*q+3] -= lik * c.w;
            }
        }
        float logd = __logf(mydiag);

        // accumulate Log-Cholesky coords (strict lower + logd in diag slot)
#pragma unroll
        for (int j = 0; j < 32; j++) {
            float v = (j < lane) ? a[j] : ((j == lane) ? logd : 0.f);
            acc[j] += v;
            accsq  += v * v;
        }
    }

    // block reduction: reuse sbuf as sred (tiles dead now)
    __syncthreads();
    float* sred = (float*)sbuf;   // WPB*PART_ENTRIES floats = 33.8KB <= 38.9KB
#pragma unroll
    for (int j = 0; j < 32; j++)
        sred[wl * PART_ENTRIES + lane * PSTRIDE + j] = acc[j];
    sred[wl * PART_ENTRIES + lane * PSTRIDE + 32] = accsq;
    __syncthreads();

    for (int e = threadIdx.x; e < PART_ENTRIES; e += THREADS) {
        float s = 0.f;
#pragma unroll
        for (int w = 0; w < WPB; w++) s += sred[w * PART_ENTRIES + e];
        g_part[e * BLOCKS + blockIdx.x] = s;   // [entry][block] -> coalesced reduce
    }
}

// ---------------------------------------------------------------------------
// k2a: deterministic tree reduction of 512 block partials per entry (coalesced).
// ---------------------------------------------------------------------------
__global__ void reduce2a() {
    __shared__ float red[BLOCKS];
    const int e = blockIdx.x;
    red[threadIdx.x] = g_part[e * BLOCKS + threadIdx.x];
    __syncthreads();
#pragma unroll
    for (int s = BLOCKS / 2; s > 0; s >>= 1) {
        if ((int)threadIdx.x < s) red[threadIdx.x] += red[threadIdx.x + s];
        __syncthreads();
    }
    if (threadIdx.x == 0) g_sums[e] = red[0];
}

// ---------------------------------------------------------------------------
// k2b: means, variance = E||x||^2 - ||Ex||^2, factor = s / sqrt(var).
// ---------------------------------------------------------------------------
__global__ void stats_pass(const float* __restrict__ s_in) {
    __shared__ float red[1024];
    const int t = threadIdx.x;               // 1024 threads
    const int i = t >> 5, j = t & 31;
    const float invM = 1.0f / (float)M_TOT;

    float mean = g_sums[i * PSTRIDE + j] * invM;   // 0 for strictly-upper slots
    g_stats[i * 32 + j] = mean;
    float val = -mean * mean;
    if (t < 32) val += g_sums[t * PSTRIDE + 32] * invM;
    red[t] = val;
    __syncthreads();
#pragma unroll
    for (int s = 512; s > 0; s >>= 1) {
        if (t < s) red[t] += red[t + s];
        __syncthreads();
    }
    if (t == 0) {
        float var = red[0];
        g_stats[1024] = s_in[0] / sqrtf(var);
    }
}

// ---------------------------------------------------------------------------
// Pass 3: coalesced column-major load of L into smem, center + geodesic
// rescale, L_out L_out^T with float4 broadcast reads (k outer, j vectorized),
// coalesced store of the SPD output through smem staging.
// ---------------------------------------------------------------------------
__global__ void __launch_bounds__(THREADS) out_pass(float* __restrict__ out) {
    __shared__ float4 sbuf[WPB * 288];       // 36.9 KB tiles
    __shared__ float  smean[32 * TS];        // padded mean (stride 36)
    __shared__ float  sfac;

    for (int e = threadIdx.x; e < 1024; e += THREADS)
        smean[(e >> 5) * TS + (e & 31)] = g_stats[e];
    if (threadIdx.x == 0) sfac = g_stats[1024];
    __syncthreads();
    const float factor = sfac;

    const int lane = threadIdx.x & 31;
    const int wl   = threadIdx.x >> 5;
    float4* tile = sbuf + wl * 288;
    float*  tf   = (float*)tile;
    const int gw = blockIdx.x * WPB + wl;

    for (int m = gw; m < M_TOT; m += NWARPS) {
        // coalesced load of column-major L -> column-major smem tile tf[col*TS + row]
        const float4* ls = (const float4*)(g_L + (size_t)m * 1024);
#pragma unroll
        for (int q = 0; q < 8; q++) {
            float4 v = ls[q * 32 + lane];    // col 4q+lane/8, rows 4(lane&7)..+3
            tile[(4 * q + (lane >> 3)) * TS4 + (lane & 7)] = v;
        }
        __syncwarp();

        // centered / rescaled own row b (lane i = row i). Upper entries are 0
        // automatically (L upper zeros, mean strict-upper zeros).
        float dL    = tf[lane * TS + lane];          // L[i][i]
        float mdiag = smean[lane * TS + lane];       // logd mean
        float edc   = __expf(factor * (__logf(dL) - mdiag));
        float b[32];
#pragma unroll
        for (int j = 0; j < 32; j++) {
            float aj = tf[j * TS + lane];            // L[i][j]  (conflict-free)
            float mj = smean[lane * TS + j];
            float v  = factor * (aj - mj);
            b[j] = (j == lane) ? edc : v;
        }
        // write b back into own column-major slots (only lane i touches (j,i))
#pragma unroll
        for (int j = 0; j < 32; j++) tf[j * TS + lane] = b[j];
        __syncwarp();

        // X_out row i: o[j] = sum_k b_i[k] * b_j[k]; k outer, j chunks of 4
        // (broadcast LDS.128 of column k = {b_j[k]}_j). b[k]=0 for k>lane
        // truncates the row; tile zeros truncate j<k.
        float o[32];
#pragma unroll
        for (int j = 0; j < 32; j++) o[j] = 0.f;
#pragma unroll
        for (int k = 0; k < 32; k++) {
            float bk = b[k];
#pragma unroll
            for (int q = k / 4; q < 8; q++) {
                float4 c = tile[k * TS4 + q];        // b_{4q..4q+3}[k], broadcast
                if (4*q+0 >= k) o[4*q+0] += bk * c.x;
                if (4*q+1 >= k) o[4*q+1] += bk * c.y;
                if (4*q+2 >= k) o[4*q+2] += bk * c.z;
                if (4*q+3 >= k) o[4*q+3] += bk * c.w;
            }
        }
        __syncwarp();   // all tile reads done before restage

        // stage o row-major, then coalesced store
#pragma unroll
        for (int q = 0; q < 8; q++)
            tile[lane * TS4 + q] = make_float4(o[4*q], o[4*q+1], o[4*q+2], o[4*q+3]);
        __syncwarp();
        float4* od = (float4*)(out + (size_t)m * 1024);
#pragma unroll
        for (int q = 0; q < 8; q++)
            od[q * 32 + lane] = tile[(4 * q + (lane >> 3)) * TS4 + (lane & 7)];
        __syncwarp();
    }
}

extern "C" void kernel_launch(void* const* d_in, const int* in_sizes, int n_in,
                              void* d_out, int out_size) {
    const float* X = (const float*)d_in[0];
    const float* s = (const float*)d_in[1];
    float* out = (float*)d_out;

    chol_pass1<<<BLOCKS, THREADS>>>(X);
    reduce2a<<<PART_ENTRIES, BLOCKS>>>();
    stats_pass<<<1, 1024>>>(s);
    out_pass<<<BLOCKS, THREADS>>>(out);
}